// round 15
// baseline (speedup 1.0000x reference)
#include <cuda_runtime.h>
#include <cuda_bf16.h>
#include <cstdint>
#include <cstddef>

#define Bc 4
#define Nc 128
#define Cc 512
#define Hc 8
#define Dc 64
#define SCALEc 6.25f
#define MTOT 65536
#define NOUT 2560
#define KDIM 512
#define NELEM 33554432

typedef unsigned short ushort_t;

// ---------------- scratch ----------------
__device__ ushort_t g_qh[(size_t)MTOT * NOUT];             // qkv bf16 hi plane
__device__ ushort_t g_ql[(size_t)MTOT * NOUT];             // qkv bf16 lo plane
__device__ float    g_scores[(size_t)32 * 128 * 128 * 128]; // term1 -> attn (in place)
__device__ ushort_t g_xh[(size_t)MTOT * KDIM];             // normalized x, bf16 hi
__device__ ushort_t g_xl[(size_t)MTOT * KDIM];             // bf16 lo
__device__ ushort_t g_wth[(size_t)NOUT * KDIM];            // W^T hi  [n][k]
__device__ ushort_t g_wtl[(size_t)NOUT * KDIM];            // W^T lo
__device__ double g_sum, g_sumsq;
__device__ float  g_mu, g_rsig;

// ---------------- helpers ----------------
__device__ __forceinline__ void split_us(float v, ushort_t& h, ushort_t& l) {
    __nv_bfloat16 hb = __float2bfloat16_rn(v);
    float r = v - __bfloat162float(hb);
    __nv_bfloat16 lb = __float2bfloat16_rn(r);
    h = __bfloat16_as_ushort(hb);
    l = __bfloat16_as_ushort(lb);
}
__device__ __forceinline__ void mma_bf16(float c[4], const unsigned a[4], const unsigned b[2]) {
    asm volatile("mma.sync.aligned.m16n8k16.row.col.f32.bf16.bf16.f32 "
                 "{%0,%1,%2,%3},{%4,%5,%6,%7},{%8,%9},{%0,%1,%2,%3};"
                 : "+f"(c[0]), "+f"(c[1]), "+f"(c[2]), "+f"(c[3])
                 : "r"(a[0]), "r"(a[1]), "r"(a[2]), "r"(a[3]), "r"(b[0]), "r"(b[1]));
}
__device__ __forceinline__ void cpa16(unsigned saddr, const void* g) {
    asm volatile("cp.async.cg.shared.global [%0], [%1], 16;\n" :: "r"(saddr), "l"(g));
}

// ---------------- stats ----------------
__global__ void k_zero() { g_sum = 0.0; g_sumsq = 0.0; }

__global__ void k_reduce(const float* __restrict__ x) {
    const float4* x4 = (const float4*)x;
    float s = 0.f, ss = 0.f;
    for (unsigned idx = blockIdx.x * blockDim.x + threadIdx.x; idx < NELEM / 4;
         idx += gridDim.x * blockDim.x) {
        float4 v = x4[idx];
        s  += v.x + v.y + v.z + v.w;
        ss += v.x * v.x + v.y * v.y + v.z * v.z + v.w * v.w;
    }
    double ds = (double)s, dss = (double)ss;
    for (int o = 16; o; o >>= 1) {
        ds  += __shfl_down_sync(0xffffffffu, ds, o);
        dss += __shfl_down_sync(0xffffffffu, dss, o);
    }
    __shared__ double sh0[8], sh1[8];
    int lane = threadIdx.x & 31, w = threadIdx.x >> 5;
    if (lane == 0) { sh0[w] = ds; sh1[w] = dss; }
    __syncthreads();
    if (threadIdx.x == 0) {
        double a = 0, b = 0;
        for (int i = 0; i < 8; i++) { a += sh0[i]; b += sh1[i]; }
        atomicAdd(&g_sum, a);
        atomicAdd(&g_sumsq, b);
    }
}

__global__ void k_finalize() {
    double cnt  = (double)NELEM;
    double mean = g_sum / cnt;
    double var  = (g_sumsq - g_sum * g_sum / cnt) / (cnt - 1.0);
    g_mu   = (float)mean;
    g_rsig = (float)(1.0 / sqrt(var));
}

// ---------------- prep: normalize + split X ----------------
__global__ __launch_bounds__(256) void k_prep_x(const float* __restrict__ x) {
    const float mu = g_mu, rs = g_rsig;
    const float4* x4 = (const float4*)x;
    for (unsigned idx = blockIdx.x * blockDim.x + threadIdx.x; idx < NELEM / 4;
         idx += gridDim.x * blockDim.x) {
        float4 v = x4[idx];
        ushort4 h, l;
        split_us((v.x - mu) * rs, h.x, l.x);
        split_us((v.y - mu) * rs, h.y, l.y);
        split_us((v.z - mu) * rs, h.z, l.z);
        split_us((v.w - mu) * rs, h.w, l.w);
        ((ushort4*)g_xh)[idx] = h;
        ((ushort4*)g_xl)[idx] = l;
    }
}

// ---------------- prep: split + transpose W -> [n][k] ----------------
__global__ __launch_bounds__(256) void k_prep_w(const float* __restrict__ w) {
    unsigned idx = blockIdx.x * blockDim.x + threadIdx.x;
    if (idx >= (unsigned)NOUT * KDIM) return;
    unsigned n = idx >> 9, k = idx & 511;
    float v = w[(size_t)k * NOUT + n];
    split_us(v, g_wth[idx], g_wtl[idx]);
}

// ---------------- QKV GEMM: pure bf16, double-buffered cp.async ----------------
// smem: 2 stages x 2 parts x 128 rows x GLDA(=16) shorts x 2 operands = 32768 B
#define GK 16
#define GLDA 16
__global__ __launch_bounds__(256) void k_gemm2() {
    __shared__ ushort_t sA[2][2][128 * GLDA];
    __shared__ ushort_t sB[2][2][128 * GLDA];
    const int tid = threadIdx.x;
    const int warp = tid >> 5, lane = tid & 31;
    const int wr = warp >> 2, wc = warp & 3;   // warp tile 64x32
    const int bm = blockIdx.y * 128, bn = blockIdx.x * 128;
    const unsigned sAb = (unsigned)__cvta_generic_to_shared(&sA[0][0][0]);
    const unsigned sBb = (unsigned)__cvta_generic_to_shared(&sB[0][0][0]);
    float acc[4][4][4] = {};

    const ushort_t* gA[2] = { g_xh, g_xl };
    const ushort_t* gB[2] = { g_wth, g_wtl };

    auto loadstage = [&](int st, int k0) {
        int row = tid >> 1, off = (tid & 1) * 8;
#pragma unroll
        for (int p = 0; p < 2; p++) {
            unsigned so = (unsigned)(((st * 2 + p) * 128 * GLDA) + row * GLDA + off) * 2;
            cpa16(sAb + so, gA[p] + (size_t)(bm + row) * KDIM + k0 + off);
            cpa16(sBb + so, gB[p] + (size_t)(bn + row) * KDIM + k0 + off);
        }
    };

    loadstage(0, 0);
    asm volatile("cp.async.commit_group;");

    int buf = 0;
    for (int it = 0; it < KDIM / GK; it++) {
        if (it + 1 < KDIM / GK) {
            loadstage(buf ^ 1, (it + 1) * GK);
            asm volatile("cp.async.commit_group;");
            asm volatile("cp.async.wait_group 1;");
        } else {
            asm volatile("cp.async.wait_group 0;");
        }
        __syncthreads();

        const ushort_t* Ah = &sA[buf][0][0];
        const ushort_t* Al = &sA[buf][1][0];
        const ushort_t* Bh = &sB[buf][0][0];
        const ushort_t* Bl = &sB[buf][1][0];
        const int rsel = lane >> 2;
        const int c2 = 2 * (lane & 3);
        unsigned ah[4][4], al[4][4], bh2[4][2], bl2[4][2];
#pragma unroll
        for (int i = 0; i < 4; i++) {
            int row = wr * 64 + i * 16 + rsel;
            ah[i][0] = *(const unsigned*)&Ah[row * GLDA + c2];
            ah[i][1] = *(const unsigned*)&Ah[(row + 8) * GLDA + c2];
            ah[i][2] = *(const unsigned*)&Ah[row * GLDA + c2 + 8];
            ah[i][3] = *(const unsigned*)&Ah[(row + 8) * GLDA + c2 + 8];
            al[i][0] = *(const unsigned*)&Al[row * GLDA + c2];
            al[i][1] = *(const unsigned*)&Al[(row + 8) * GLDA + c2];
            al[i][2] = *(const unsigned*)&Al[row * GLDA + c2 + 8];
            al[i][3] = *(const unsigned*)&Al[(row + 8) * GLDA + c2 + 8];
        }
#pragma unroll
        for (int j = 0; j < 4; j++) {
            int n = wc * 32 + j * 8 + rsel;
            bh2[j][0] = *(const unsigned*)&Bh[n * GLDA + c2];
            bh2[j][1] = *(const unsigned*)&Bh[n * GLDA + c2 + 8];
            bl2[j][0] = *(const unsigned*)&Bl[n * GLDA + c2];
            bl2[j][1] = *(const unsigned*)&Bl[n * GLDA + c2 + 8];
        }
#pragma unroll
        for (int i = 0; i < 4; i++)
#pragma unroll
            for (int j = 0; j < 4; j++) {
                mma_bf16(acc[i][j], ah[i], bh2[j]);
                mma_bf16(acc[i][j], ah[i], bl2[j]);
                mma_bf16(acc[i][j], al[i], bh2[j]);
            }
        __syncthreads();
        buf ^= 1;
    }
    // epilogue: split fp32 acc -> bf16 hi/lo planes
#pragma unroll
    for (int i = 0; i < 4; i++) {
        int m0 = bm + wr * 64 + i * 16 + (lane >> 2);
#pragma unroll
        for (int j = 0; j < 4; j++) {
            int n0 = bn + wc * 32 + j * 8 + (lane & 3) * 2;
            ushort_t h0, l0, h1, l1;
            split_us(acc[i][j][0], h0, l0);
            split_us(acc[i][j][1], h1, l1);
            *(ushort2*)&g_qh[(size_t)m0 * NOUT + n0] = make_ushort2(h0, h1);
            *(ushort2*)&g_ql[(size_t)m0 * NOUT + n0] = make_ushort2(l0, l1);
            split_us(acc[i][j][2], h0, l0);
            split_us(acc[i][j][3], h1, l1);
            *(ushort2*)&g_qh[(size_t)(m0 + 8) * NOUT + n0] = make_ushort2(h0, h1);
            *(ushort2*)&g_ql[(size_t)(m0 + 8) * NOUT + n0] = make_ushort2(l0, l1);
        }
    }
}

// ---------------- scores term1 (bf16x3 from planes, write scratch) ----------------
#define LDK 18
__global__ __launch_bounds__(256) void k_scores1(float* __restrict__ scores) {
    __shared__ ushort_t Qh[128][LDK], Ql[128][LDK];
    __shared__ ushort_t Kh[128][LDK], Kl[128][LDK];
    const int blk = blockIdx.x;
    const int bh = blk >> 7, fix = blk & 127;
    const int b = bh >> 3, h = bh & 7;
    const int tid = threadIdx.x;
    const int warp = tid >> 5, lane = tid & 31;
    const int wr = warp >> 2, wc = warp & 3;

    const size_t qoff = (size_t)(b * 16384 + fix * 128) * NOUT + h * 64;
    const size_t koff = qoff + 512;
    const size_t rstride = NOUT;

    float acc[4][4][4] = {};
    for (int d0 = 0; d0 < 64; d0 += 16) {
#pragma unroll
        for (int it = 0; it < 2; it++) {
            int idx = it * 256 + tid;
            int r = idx >> 2, q = (idx & 3) * 4;
            size_t o = (size_t)r * rstride + d0 + q;
            ushort4 qh4 = *(const ushort4*)(g_qh + qoff + o);
            ushort4 ql4 = *(const ushort4*)(g_ql + qoff + o);
            ushort4 kh4 = *(const ushort4*)(g_qh + koff + o);
            ushort4 kl4 = *(const ushort4*)(g_ql + koff + o);
            *(ushort2*)&Qh[r][q]     = make_ushort2(qh4.x, qh4.y);
            *(ushort2*)&Qh[r][q + 2] = make_ushort2(qh4.z, qh4.w);
            *(ushort2*)&Ql[r][q]     = make_ushort2(ql4.x, ql4.y);
            *(ushort2*)&Ql[r][q + 2] = make_ushort2(ql4.z, ql4.w);
            *(ushort2*)&Kh[r][q]     = make_ushort2(kh4.x, kh4.y);
            *(ushort2*)&Kh[r][q + 2] = make_ushort2(kh4.z, kh4.w);
            *(ushort2*)&Kl[r][q]     = make_ushort2(kl4.x, kl4.y);
            *(ushort2*)&Kl[r][q + 2] = make_ushort2(kl4.z, kl4.w);
        }
        __syncthreads();
        const int c2 = 2 * (lane & 3), rsel = lane >> 2;
        unsigned ah[4][4], al[4][4], bh2[4][2], bl2[4][2];
#pragma unroll
        for (int i = 0; i < 4; i++) {
            int row = wr * 64 + i * 16 + rsel;
            ah[i][0] = *(const unsigned*)&Qh[row][c2];
            ah[i][1] = *(const unsigned*)&Qh[row + 8][c2];
            ah[i][2] = *(const unsigned*)&Qh[row][c2 + 8];
            ah[i][3] = *(const unsigned*)&Qh[row + 8][c2 + 8];
            al[i][0] = *(const unsigned*)&Ql[row][c2];
            al[i][1] = *(const unsigned*)&Ql[row + 8][c2];
            al[i][2] = *(const unsigned*)&Ql[row][c2 + 8];
            al[i][3] = *(const unsigned*)&Ql[row + 8][c2 + 8];
        }
#pragma unroll
        for (int j = 0; j < 4; j++) {
            int n = wc * 32 + j * 8 + rsel;
            bh2[j][0] = *(const unsigned*)&Kh[n][c2];
            bh2[j][1] = *(const unsigned*)&Kh[n][c2 + 8];
            bl2[j][0] = *(const unsigned*)&Kl[n][c2];
            bl2[j][1] = *(const unsigned*)&Kl[n][c2 + 8];
        }
#pragma unroll
        for (int i = 0; i < 4; i++)
#pragma unroll
            for (int j = 0; j < 4; j++) {
                mma_bf16(acc[i][j], ah[i], bh2[j]);
                mma_bf16(acc[i][j], ah[i], bl2[j]);
                mma_bf16(acc[i][j], al[i], bh2[j]);
            }
        __syncthreads();
    }
#pragma unroll
    for (int i = 0; i < 4; i++) {
        int row = wr * 64 + i * 16 + (lane >> 2);
#pragma unroll
        for (int j = 0; j < 4; j++) {
            int col = wc * 32 + j * 8 + (lane & 3) * 2;
            float* p0 = scores + (size_t)blk * 16384 + (size_t)row * 128 + col;
            float* p1 = p0 + 8 * 128;
            *(float2*)p0 = make_float2(SCALEc * acc[i][j][0], SCALEc * acc[i][j][1]);
            *(float2*)p1 = make_float2(SCALEc * acc[i][j][2], SCALEc * acc[i][j][3]);
        }
    }
}

// ---------------- scores term2 + softmax (fused), in-place attn ----------------
__global__ __launch_bounds__(256) void k_scores2_sm(float* __restrict__ scores) {
    __shared__ ushort_t Qh[128][LDK], Ql[128][LDK];
    __shared__ ushort_t Kh[128][LDK], Kl[128][LDK];
    __shared__ float rmax[128][4];
    __shared__ float rsum[128][4];
    const int blk = blockIdx.x;
    const int bh = blk >> 7, fix = blk & 127;       // fix = j
    const int b = bh >> 3, h = bh & 7;
    const int tid = threadIdx.x;
    const int warp = tid >> 5, lane = tid & 31;
    const int wr = warp >> 2, wc = warp & 3;

    const size_t qoff = (size_t)(b * 16384 + fix) * NOUT + h * 64;
    const size_t koff = qoff + 1024;
    const size_t rstride = (size_t)128 * NOUT;

    float acc[4][4][4] = {};
    for (int d0 = 0; d0 < 64; d0 += 16) {
#pragma unroll
        for (int it = 0; it < 2; it++) {
            int idx = it * 256 + tid;
            int r = idx >> 2, q = (idx & 3) * 4;
            size_t o = (size_t)r * rstride + d0 + q;
            ushort4 qh4 = *(const ushort4*)(g_qh + qoff + o);
            ushort4 ql4 = *(const ushort4*)(g_ql + qoff + o);
            ushort4 kh4 = *(const ushort4*)(g_qh + koff + o);
            ushort4 kl4 = *(const ushort4*)(g_ql + koff + o);
            *(ushort2*)&Qh[r][q]     = make_ushort2(qh4.x, qh4.y);
            *(ushort2*)&Qh[r][q + 2] = make_ushort2(qh4.z, qh4.w);
            *(ushort2*)&Ql[r][q]     = make_ushort2(ql4.x, ql4.y);
            *(ushort2*)&Ql[r][q + 2] = make_ushort2(ql4.z, ql4.w);
            *(ushort2*)&Kh[r][q]     = make_ushort2(kh4.x, kh4.y);
            *(ushort2*)&Kh[r][q + 2] = make_ushort2(kh4.z, kh4.w);
            *(ushort2*)&Kl[r][q]     = make_ushort2(kl4.x, kl4.y);
            *(ushort2*)&Kl[r][q + 2] = make_ushort2(kl4.z, kl4.w);
        }
        __syncthreads();
        const int c2 = 2 * (lane & 3), rsel = lane >> 2;
        unsigned ah[4][4], al[4][4], bh2[4][2], bl2[4][2];
#pragma unroll
        for (int i = 0; i < 4; i++) {
            int row = wr * 64 + i * 16 + rsel;
            ah[i][0] = *(const unsigned*)&Qh[row][c2];
            ah[i][1] = *(const unsigned*)&Qh[row + 8][c2];
            ah[i][2] = *(const unsigned*)&Qh[row][c2 + 8];
            ah[i][3] = *(const unsigned*)&Qh[row + 8][c2 + 8];
            al[i][0] = *(const unsigned*)&Ql[row][c2];
            al[i][1] = *(const unsigned*)&Ql[row + 8][c2];
            al[i][2] = *(const unsigned*)&Ql[row][c2 + 8];
            al[i][3] = *(const unsigned*)&Ql[row + 8][c2 + 8];
        }
#pragma unroll
        for (int j = 0; j < 4; j++) {
            int n = wc * 32 + j * 8 + rsel;
            bh2[j][0] = *(const unsigned*)&Kh[n][c2];
            bh2[j][1] = *(const unsigned*)&Kh[n][c2 + 8];
            bl2[j][0] = *(const unsigned*)&Kl[n][c2];
            bl2[j][1] = *(const unsigned*)&Kl[n][c2 + 8];
        }
#pragma unroll
        for (int i = 0; i < 4; i++)
#pragma unroll
            for (int j = 0; j < 4; j++) {
                mma_bf16(acc[i][j], ah[i], bh2[j]);
                mma_bf16(acc[i][j], ah[i], bl2[j]);
                mma_bf16(acc[i][j], al[i], bh2[j]);
            }
        __syncthreads();
    }

    const int rsel = lane >> 2;
    float* base = scores + (size_t)bh * 2097152 + (size_t)fix * 128;
#pragma unroll
    for (int t = 0; t < 4; t++) {
        int row = wr * 64 + t * 16 + rsel;
#pragma unroll
        for (int j = 0; j < 4; j++) {
            int col = wc * 32 + j * 8 + (lane & 3) * 2;
            float2 o0 = *(float2*)(base + (size_t)row * 16384 + col);
            float2 o1 = *(float2*)(base + (size_t)(row + 8) * 16384 + col);
            acc[t][j][0] = SCALEc * acc[t][j][0] + o0.x;
            acc[t][j][1] = SCALEc * acc[t][j][1] + o0.y;
            acc[t][j][2] = SCALEc * acc[t][j][2] + o1.x;
            acc[t][j][3] = SCALEc * acc[t][j][3] + o1.y;
        }
    }
#pragma unroll
    for (int t = 0; t < 4; t++) {
#pragma unroll
        for (int r = 0; r < 2; r++) {
            float m = -1e30f;
#pragma unroll
            for (int j = 0; j < 4; j++)
                m = fmaxf(m, fmaxf(acc[t][j][2 * r], acc[t][j][2 * r + 1]));
            m = fmaxf(m, __shfl_xor_sync(0xffffffffu, m, 1));
            m = fmaxf(m, __shfl_xor_sync(0xffffffffu, m, 2));
            if ((lane & 3) == 0) rmax[wr * 64 + t * 16 + rsel + r * 8][wc] = m;
        }
    }
    __syncthreads();
#pragma unroll
    for (int t = 0; t < 4; t++) {
#pragma unroll
        for (int r = 0; r < 2; r++) {
            int row = wr * 64 + t * 16 + rsel + r * 8;
            float4 mv = *(float4*)rmax[row];
            float gm = fmaxf(fmaxf(mv.x, mv.y), fmaxf(mv.z, mv.w));
            float ls = 0.f;
#pragma unroll
            for (int j = 0; j < 4; j++) {
                float e0 = __expf(acc[t][j][2 * r] - gm);
                float e1 = __expf(acc[t][j][2 * r + 1] - gm);
                acc[t][j][2 * r] = e0; acc[t][j][2 * r + 1] = e1;
                ls += e0 + e1;
            }
            ls += __shfl_xor_sync(0xffffffffu, ls, 1);
            ls += __shfl_xor_sync(0xffffffffu, ls, 2);
            if ((lane & 3) == 0) rsum[row][wc] = ls;
        }
    }
    __syncthreads();
#pragma unroll
    for (int t = 0; t < 4; t++) {
        int row = wr * 64 + t * 16 + rsel;
        float4 s0 = *(float4*)rsum[row];
        float4 s1 = *(float4*)rsum[row + 8];
        float inv0 = 1.f / (s0.x + s0.y + s0.z + s0.w);
        float inv1 = 1.f / (s1.x + s1.y + s1.z + s1.w);
#pragma unroll
        for (int j = 0; j < 4; j++) {
            int col = wc * 32 + j * 8 + (lane & 3) * 2;
            *(float2*)(base + (size_t)row * 16384 + col) =
                make_float2(acc[t][j][0] * inv0, acc[t][j][1] * inv0);
            *(float2*)(base + (size_t)(row + 8) * 16384 + col) =
                make_float2(acc[t][j][2] * inv1, acc[t][j][3] * inv1);
        }
    }
}

// ---------------- output (bf16: attn hi/lo split in-loop, v from planes) ----------------
template <int MODE>
__global__ __launch_bounds__(256) void k_out_bf(const float* __restrict__ scores,
                                                float* __restrict__ out) {
    __shared__ ushort_t Ath[128][LDK], Atl[128][LDK];   // attn [row][k]
    __shared__ ushort_t Vh[64][LDK], Vl[64][LDK];       // v    [d][k]
    const int blk = blockIdx.x;
    const int bh = blk >> 7, fix = blk & 127;
    const int b = bh >> 3, h = bh & 7;
    const int tid = threadIdx.x;
    const int warp = tid >> 5, lane = tid & 31;
    const int wr = warp >> 2, wc = warp & 3;   // warp tile 64x16

    const float* arow; size_t astride;
    size_t voff; size_t vstride;
    float* obase; size_t ostride;
    if (MODE == 0) {
        arow = scores + (size_t)blk * 16384;  astride = 128;
        voff = (size_t)(b * 16384 + fix * 128) * NOUT + 1536 + h * 64;
        vstride = NOUT;
        obase = out + ((size_t)(b * 128 + fix) * 128) * Cc + h * 64;
        ostride = Cc;
    } else {
        arow = scores + (size_t)bh * 2097152 + (size_t)fix * 128;  astride = 16384;
        voff = (size_t)(b * 16384 + fix) * NOUT + 2048 + h * 64;
        vstride = (size_t)128 * NOUT;
        obase = out + ((size_t)(b * 128) * 128 + fix) * Cc + h * 64;
        ostride = (size_t)128 * Cc;
    }

    float acc[4][2][4] = {};
    for (int k0 = 0; k0 < 128; k0 += 16) {
#pragma unroll
        for (int it = 0; it < 2; it++) {   // attn: 128 rows x 16 k, split fp32 -> hi/lo
            int idx = it * 256 + tid;
            int r = idx >> 2, q = (idx & 3) * 4;
            float4 av = *(const float4*)(arow + (size_t)r * astride + k0 + q);
            ushort_t h0, l0, h1, l1;
            split_us(av.x, h0, l0); split_us(av.y, h1, l1);
            *(ushort2*)&Ath[r][q] = make_ushort2(h0, h1);
            *(ushort2*)&Atl[r][q] = make_ushort2(l0, l1);
            split_us(av.z, h0, l0); split_us(av.w, h1, l1);
            *(ushort2*)&Ath[r][q + 2] = make_ushort2(h0, h1);
            *(ushort2*)&Atl[r][q + 2] = make_ushort2(l0, l1);
        }
        {   // v: 16 k rows x 64 d from planes, transpose into [d][k]
            int kk = tid >> 4, d4 = (tid & 15) * 4;
            size_t o = voff + (size_t)(k0 + kk) * vstride + d4;
            ushort4 vh4 = *(const ushort4*)(g_qh + o);
            ushort4 vl4 = *(const ushort4*)(g_ql + o);
            Vh[d4 + 0][kk] = vh4.x; Vh[d4 + 1][kk] = vh4.y;
            Vh[d4 + 2][kk] = vh4.z; Vh[d4 + 3][kk] = vh4.w;
            Vl[d4 + 0][kk] = vl4.x; Vl[d4 + 1][kk] = vl4.y;
            Vl[d4 + 2][kk] = vl4.z; Vl[d4 + 3][kk] = vl4.w;
        }
        __syncthreads();
        const int c2 = 2 * (lane & 3), rsel = lane >> 2;
        unsigned ah[4][4], al[4][4], bh2[2][2], bl2[2][2];
#pragma unroll
        for (int i = 0; i < 4; i++) {
            int row = wr * 64 + i * 16 + rsel;
            ah[i][0] = *(const unsigned*)&Ath[row][c2];
            ah[i][1] = *(const unsigned*)&Ath[row + 8][c2];
            ah[i][2] = *(const unsigned*)&Ath[row][c2 + 8];
            ah[i][3] = *(const unsigned*)&Ath[row + 8][c2 + 8];
            al[i][0] = *(const unsigned*)&Atl[row][c2];
            al[i][1] = *(const unsigned*)&Atl[row + 8][c2];
            al[i][2] = *(const unsigned*)&Atl[row][c2 + 8];
            al[i][3] = *(const unsigned*)&Atl[row + 8][c2 + 8];
        }
#pragma unroll
        for (int j = 0; j < 2; j++) {
            int n = wc * 16 + j * 8 + rsel;
            bh2[j][0] = *(const unsigned*)&Vh[n][c2];
            bh2[j][1] = *(const unsigned*)&Vh[n][c2 + 8];
            bl2[j][0] = *(const unsigned*)&Vl[n][c2];
            bl2[j][1] = *(const unsigned*)&Vl[n][c2 + 8];
        }
#pragma unroll
        for (int i = 0; i < 4; i++)
#pragma unroll
            for (int j = 0; j < 2; j++) {
                mma_bf16(acc[i][j], ah[i], bh2[j]);
                mma_bf16(acc[i][j], ah[i], bl2[j]);
                mma_bf16(acc[i][j], al[i], bh2[j]);
            }
        __syncthreads();
    }
#pragma unroll
    for (int i = 0; i < 4; i++) {
        int row = wr * 64 + i * 16 + (lane >> 2);
#pragma unroll
        for (int j = 0; j < 2; j++) {
            int col = wc * 16 + j * 8 + (lane & 3) * 2;
            float* p0 = obase + (size_t)row * ostride + col;
            float* p1 = obase + (size_t)(row + 8) * ostride + col;
            if (MODE == 0) {
                *(float2*)p0 = make_float2(acc[i][j][0], acc[i][j][1]);
                *(float2*)p1 = make_float2(acc[i][j][2], acc[i][j][3]);
            } else {
                float2 o0 = *(float2*)p0, o1 = *(float2*)p1;
                o0.x += acc[i][j][0]; o0.y += acc[i][j][1];
                o1.x += acc[i][j][2]; o1.y += acc[i][j][3];
                *(float2*)p0 = o0; *(float2*)p1 = o1;
            }
        }
    }
}

// ---------------- launch ----------------
extern "C" void kernel_launch(void* const* d_in, const int* in_sizes, int n_in,
                              void* d_out, int out_size) {
    const float* x = (const float*)d_in[0];
    const float* w = (const float*)d_in[1];
    float* out = (float*)d_out;

    float* scores;
    cudaGetSymbolAddress((void**)&scores, g_scores);

    k_zero<<<1, 1>>>();
    k_reduce<<<1024, 256>>>(x);
    k_finalize<<<1, 1>>>();
    k_prep_x<<<2048, 256>>>(x);
    k_prep_w<<<(NOUT * KDIM + 255) / 256, 256>>>(w);
    k_gemm2<<<dim3(NOUT / 128, MTOT / 128), 256>>>();
    k_scores1<<<4096, 256>>>(scores);
    k_scores2_sm<<<4096, 256>>>(scores);
    k_out_bf<0><<<4096, 256>>>(scores, out);
    k_out_bf<1><<<4096, 256>>>(scores, out);
}

// round 17
// speedup vs baseline: 1.0254x; 1.0254x over previous
#include <cuda_runtime.h>
#include <cuda_bf16.h>
#include <cstdint>
#include <cstddef>

#define Bc 4
#define Nc 128
#define Cc 512
#define Hc 8
#define Dc 64
#define SCALEc 6.25f
#define MTOT 65536
#define NOUT 2560
#define KDIM 512
#define NELEM 33554432

typedef unsigned short ushort_t;

// ---------------- scratch ----------------
__device__ float    g_qkv[(size_t)MTOT * NOUT];            // fp32 (v region used)
__device__ ushort_t g_qh[(size_t)MTOT * NOUT];             // qkv bf16 hi plane (q/k region)
__device__ ushort_t g_ql[(size_t)MTOT * NOUT];             // qkv bf16 lo plane
__device__ float    g_scores[(size_t)32 * 128 * 128 * 128]; // term1 -> attn (in place)
__device__ ushort_t g_xh[(size_t)MTOT * KDIM];
__device__ ushort_t g_xl[(size_t)MTOT * KDIM];
__device__ ushort_t g_wth[(size_t)NOUT * KDIM];
__device__ ushort_t g_wtl[(size_t)NOUT * KDIM];
__device__ double g_sum, g_sumsq;
__device__ float  g_mu, g_rsig;

// ---------------- helpers ----------------
__device__ __forceinline__ void split_us(float v, ushort_t& h, ushort_t& l) {
    __nv_bfloat16 hb = __float2bfloat16_rn(v);
    float r = v - __bfloat162float(hb);
    __nv_bfloat16 lb = __float2bfloat16_rn(r);
    h = __bfloat16_as_ushort(hb);
    l = __bfloat16_as_ushort(lb);
}
__device__ __forceinline__ void mma_bf16(float c[4], const unsigned a[4], const unsigned b[2]) {
    asm volatile("mma.sync.aligned.m16n8k16.row.col.f32.bf16.bf16.f32 "
                 "{%0,%1,%2,%3},{%4,%5,%6,%7},{%8,%9},{%0,%1,%2,%3};"
                 : "+f"(c[0]), "+f"(c[1]), "+f"(c[2]), "+f"(c[3])
                 : "r"(a[0]), "r"(a[1]), "r"(a[2]), "r"(a[3]), "r"(b[0]), "r"(b[1]));
}
__device__ __forceinline__ void mma_tf32(float c[4], const unsigned a[4], const unsigned b[2]) {
    asm volatile("mma.sync.aligned.m16n8k8.row.col.f32.tf32.tf32.f32 "
                 "{%0,%1,%2,%3},{%4,%5,%6,%7},{%8,%9},{%0,%1,%2,%3};"
                 : "+f"(c[0]), "+f"(c[1]), "+f"(c[2]), "+f"(c[3])
                 : "r"(a[0]), "r"(a[1]), "r"(a[2]), "r"(a[3]), "r"(b[0]), "r"(b[1]));
}
__device__ __forceinline__ unsigned f2tf(float f) {
    unsigned r; asm("cvt.rna.tf32.f32 %0, %1;" : "=r"(r) : "f"(f)); return r;
}
__device__ __forceinline__ void split_tf(float v, unsigned& h, unsigned& l) {
    asm("cvt.rna.tf32.f32 %0, %1;" : "=r"(h) : "f"(v));
    float hf = __uint_as_float(h);
    asm("cvt.rna.tf32.f32 %0, %1;" : "=r"(l) : "f"(v - hf));
}
__device__ __forceinline__ void cpa16(unsigned saddr, const void* g) {
    asm volatile("cp.async.cg.shared.global [%0], [%1], 16;\n" :: "r"(saddr), "l"(g));
}

// ---------------- stats ----------------
__global__ void k_zero() { g_sum = 0.0; g_sumsq = 0.0; }

__global__ void k_reduce(const float* __restrict__ x) {
    const float4* x4 = (const float4*)x;
    float s = 0.f, ss = 0.f;
    for (unsigned idx = blockIdx.x * blockDim.x + threadIdx.x; idx < NELEM / 4;
         idx += gridDim.x * blockDim.x) {
        float4 v = x4[idx];
        s  += v.x + v.y + v.z + v.w;
        ss += v.x * v.x + v.y * v.y + v.z * v.z + v.w * v.w;
    }
    double ds = (double)s, dss = (double)ss;
    for (int o = 16; o; o >>= 1) {
        ds  += __shfl_down_sync(0xffffffffu, ds, o);
        dss += __shfl_down_sync(0xffffffffu, dss, o);
    }
    __shared__ double sh0[8], sh1[8];
    int lane = threadIdx.x & 31, w = threadIdx.x >> 5;
    if (lane == 0) { sh0[w] = ds; sh1[w] = dss; }
    __syncthreads();
    if (threadIdx.x == 0) {
        double a = 0, b = 0;
        for (int i = 0; i < 8; i++) { a += sh0[i]; b += sh1[i]; }
        atomicAdd(&g_sum, a);
        atomicAdd(&g_sumsq, b);
    }
}

__global__ void k_finalize() {
    double cnt  = (double)NELEM;
    double mean = g_sum / cnt;
    double var  = (g_sumsq - g_sum * g_sum / cnt) / (cnt - 1.0);
    g_mu   = (float)mean;
    g_rsig = (float)(1.0 / sqrt(var));
}

// ---------------- prep: normalize + split X ----------------
__global__ __launch_bounds__(256) void k_prep_x(const float* __restrict__ x) {
    const float mu = g_mu, rs = g_rsig;
    const float4* x4 = (const float4*)x;
    for (unsigned idx = blockIdx.x * blockDim.x + threadIdx.x; idx < NELEM / 4;
         idx += gridDim.x * blockDim.x) {
        float4 v = x4[idx];
        ushort4 h, l;
        split_us((v.x - mu) * rs, h.x, l.x);
        split_us((v.y - mu) * rs, h.y, l.y);
        split_us((v.z - mu) * rs, h.z, l.z);
        split_us((v.w - mu) * rs, h.w, l.w);
        ((ushort4*)g_xh)[idx] = h;
        ((ushort4*)g_xl)[idx] = l;
    }
}

// ---------------- prep: split + transpose W -> [n][k] ----------------
__global__ __launch_bounds__(256) void k_prep_w(const float* __restrict__ w) {
    unsigned idx = blockIdx.x * blockDim.x + threadIdx.x;
    if (idx >= (unsigned)NOUT * KDIM) return;
    unsigned n = idx >> 9, k = idx & 511;
    float v = w[(size_t)k * NOUT + n];
    split_us(v, g_wth[idx], g_wtl[idx]);
}

// ---------------- QKV GEMM: pure bf16, double-buffered cp.async ----------------
#define GK 16
#define GLDA 16
__global__ __launch_bounds__(256) void k_gemm2() {
    __shared__ ushort_t sA[2][2][128 * GLDA];
    __shared__ ushort_t sB[2][2][128 * GLDA];
    const int tid = threadIdx.x;
    const int warp = tid >> 5, lane = tid & 31;
    const int wr = warp >> 2, wc = warp & 3;   // warp tile 64x32
    const int bm = blockIdx.y * 128, bn = blockIdx.x * 128;
    const unsigned sAb = (unsigned)__cvta_generic_to_shared(&sA[0][0][0]);
    const unsigned sBb = (unsigned)__cvta_generic_to_shared(&sB[0][0][0]);
    float acc[4][4][4] = {};

    const ushort_t* gA[2] = { g_xh, g_xl };
    const ushort_t* gB[2] = { g_wth, g_wtl };

    auto loadstage = [&](int st, int k0) {
        int row = tid >> 1, off = (tid & 1) * 8;
#pragma unroll
        for (int p = 0; p < 2; p++) {
            unsigned so = (unsigned)(((st * 2 + p) * 128 * GLDA) + row * GLDA + off) * 2;
            cpa16(sAb + so, gA[p] + (size_t)(bm + row) * KDIM + k0 + off);
            cpa16(sBb + so, gB[p] + (size_t)(bn + row) * KDIM + k0 + off);
        }
    };

    loadstage(0, 0);
    asm volatile("cp.async.commit_group;");

    int buf = 0;
    for (int it = 0; it < KDIM / GK; it++) {
        if (it + 1 < KDIM / GK) {
            loadstage(buf ^ 1, (it + 1) * GK);
            asm volatile("cp.async.commit_group;");
            asm volatile("cp.async.wait_group 1;");
        } else {
            asm volatile("cp.async.wait_group 0;");
        }
        __syncthreads();

        const ushort_t* Ah = &sA[buf][0][0];
        const ushort_t* Al = &sA[buf][1][0];
        const ushort_t* Bh = &sB[buf][0][0];
        const ushort_t* Bl = &sB[buf][1][0];
        const int rsel = lane >> 2;
        const int c2 = 2 * (lane & 3);
        unsigned ah[4][4], al[4][4], bh2[4][2], bl2[4][2];
#pragma unroll
        for (int i = 0; i < 4; i++) {
            int row = wr * 64 + i * 16 + rsel;
            ah[i][0] = *(const unsigned*)&Ah[row * GLDA + c2];
            ah[i][1] = *(const unsigned*)&Ah[(row + 8) * GLDA + c2];
            ah[i][2] = *(const unsigned*)&Ah[row * GLDA + c2 + 8];
            ah[i][3] = *(const unsigned*)&Ah[(row + 8) * GLDA + c2 + 8];
            al[i][0] = *(const unsigned*)&Al[row * GLDA + c2];
            al[i][1] = *(const unsigned*)&Al[(row + 8) * GLDA + c2];
            al[i][2] = *(const unsigned*)&Al[row * GLDA + c2 + 8];
            al[i][3] = *(const unsigned*)&Al[(row + 8) * GLDA + c2 + 8];
        }
#pragma unroll
        for (int j = 0; j < 4; j++) {
            int n = wc * 32 + j * 8 + rsel;
            bh2[j][0] = *(const unsigned*)&Bh[n * GLDA + c2];
            bh2[j][1] = *(const unsigned*)&Bh[n * GLDA + c2 + 8];
            bl2[j][0] = *(const unsigned*)&Bl[n * GLDA + c2];
            bl2[j][1] = *(const unsigned*)&Bl[n * GLDA + c2 + 8];
        }
#pragma unroll
        for (int i = 0; i < 4; i++)
#pragma unroll
            for (int j = 0; j < 4; j++) {
                mma_bf16(acc[i][j], ah[i], bh2[j]);
                mma_bf16(acc[i][j], ah[i], bl2[j]);
                mma_bf16(acc[i][j], al[i], bh2[j]);
            }
        __syncthreads();
        buf ^= 1;
    }
    // epilogue: q/k/k2 blocks (bn < 1536) -> bf16 planes; v blocks -> fp32
    if (bn < 1536) {
#pragma unroll
        for (int i = 0; i < 4; i++) {
            int m0 = bm + wr * 64 + i * 16 + (lane >> 2);
#pragma unroll
            for (int j = 0; j < 4; j++) {
                int n0 = bn + wc * 32 + j * 8 + (lane & 3) * 2;
                ushort_t h0, l0, h1, l1;
                split_us(acc[i][j][0], h0, l0);
                split_us(acc[i][j][1], h1, l1);
                *(ushort2*)&g_qh[(size_t)m0 * NOUT + n0] = make_ushort2(h0, h1);
                *(ushort2*)&g_ql[(size_t)m0 * NOUT + n0] = make_ushort2(l0, l1);
                split_us(acc[i][j][2], h0, l0);
                split_us(acc[i][j][3], h1, l1);
                *(ushort2*)&g_qh[(size_t)(m0 + 8) * NOUT + n0] = make_ushort2(h0, h1);
                *(ushort2*)&g_ql[(size_t)(m0 + 8) * NOUT + n0] = make_ushort2(l0, l1);
            }
        }
    } else {
#pragma unroll
        for (int i = 0; i < 4; i++) {
            int m0 = bm + wr * 64 + i * 16 + (lane >> 2);
#pragma unroll
            for (int j = 0; j < 4; j++) {
                int n0 = bn + wc * 32 + j * 8 + (lane & 3) * 2;
                *(float2*)&g_qkv[(size_t)m0 * NOUT + n0] = make_float2(acc[i][j][0], acc[i][j][1]);
                *(float2*)&g_qkv[(size_t)(m0 + 8) * NOUT + n0] = make_float2(acc[i][j][2], acc[i][j][3]);
            }
        }
    }
}

// ---------------- scores term1 (planes, no split) ----------------
#define LDK 18
__global__ __launch_bounds__(256) void k_scores1(float* __restrict__ scores) {
    __shared__ ushort_t Qh[128][LDK], Ql[128][LDK];
    __shared__ ushort_t Kh[128][LDK], Kl[128][LDK];
    const int blk = blockIdx.x;
    const int bh = blk >> 7, fix = blk & 127;
    const int b = bh >> 3, h = bh & 7;
    const int tid = threadIdx.x;
    const int warp = tid >> 5, lane = tid & 31;
    const int wr = warp >> 2, wc = warp & 3;

    const size_t qoff = (size_t)(b * 16384 + fix * 128) * NOUT + h * 64;
    const size_t koff = qoff + 512;
    const size_t rstride = NOUT;

    float acc[4][4][4] = {};
    for (int d0 = 0; d0 < 64; d0 += 16) {
#pragma unroll
        for (int it = 0; it < 2; it++) {
            int idx = it * 256 + tid;
            int r = idx >> 2, q = (idx & 3) * 4;
            size_t o = (size_t)r * rstride + d0 + q;
            ushort4 qh4 = *(const ushort4*)(g_qh + qoff + o);
            ushort4 ql4 = *(const ushort4*)(g_ql + qoff + o);
            ushort4 kh4 = *(const ushort4*)(g_qh + koff + o);
            ushort4 kl4 = *(const ushort4*)(g_ql + koff + o);
            *(ushort2*)&Qh[r][q]     = make_ushort2(qh4.x, qh4.y);
            *(ushort2*)&Qh[r][q + 2] = make_ushort2(qh4.z, qh4.w);
            *(ushort2*)&Ql[r][q]     = make_ushort2(ql4.x, ql4.y);
            *(ushort2*)&Ql[r][q + 2] = make_ushort2(ql4.z, ql4.w);
            *(ushort2*)&Kh[r][q]     = make_ushort2(kh4.x, kh4.y);
            *(ushort2*)&Kh[r][q + 2] = make_ushort2(kh4.z, kh4.w);
            *(ushort2*)&Kl[r][q]     = make_ushort2(kl4.x, kl4.y);
            *(ushort2*)&Kl[r][q + 2] = make_ushort2(kl4.z, kl4.w);
        }
        __syncthreads();
        const int c2 = 2 * (lane & 3), rsel = lane >> 2;
        unsigned ah[4][4], al[4][4], bh2[4][2], bl2[4][2];
#pragma unroll
        for (int i = 0; i < 4; i++) {
            int row = wr * 64 + i * 16 + rsel;
            ah[i][0] = *(const unsigned*)&Qh[row][c2];
            ah[i][1] = *(const unsigned*)&Qh[row + 8][c2];
            ah[i][2] = *(const unsigned*)&Qh[row][c2 + 8];
            ah[i][3] = *(const unsigned*)&Qh[row + 8][c2 + 8];
            al[i][0] = *(const unsigned*)&Ql[row][c2];
            al[i][1] = *(const unsigned*)&Ql[row + 8][c2];
            al[i][2] = *(const unsigned*)&Ql[row][c2 + 8];
            al[i][3] = *(const unsigned*)&Ql[row + 8][c2 + 8];
        }
#pragma unroll
        for (int j = 0; j < 4; j++) {
            int n = wc * 32 + j * 8 + rsel;
            bh2[j][0] = *(const unsigned*)&Kh[n][c2];
            bh2[j][1] = *(const unsigned*)&Kh[n][c2 + 8];
            bl2[j][0] = *(const unsigned*)&Kl[n][c2];
            bl2[j][1] = *(const unsigned*)&Kl[n][c2 + 8];
        }
#pragma unroll
        for (int i = 0; i < 4; i++)
#pragma unroll
            for (int j = 0; j < 4; j++) {
                mma_bf16(acc[i][j], ah[i], bh2[j]);
                mma_bf16(acc[i][j], ah[i], bl2[j]);
                mma_bf16(acc[i][j], al[i], bh2[j]);
            }
        __syncthreads();
    }
#pragma unroll
    for (int i = 0; i < 4; i++) {
        int row = wr * 64 + i * 16 + (lane >> 2);
#pragma unroll
        for (int j = 0; j < 4; j++) {
            int col = wc * 32 + j * 8 + (lane & 3) * 2;
            float* p0 = scores + (size_t)blk * 16384 + (size_t)row * 128 + col;
            float* p1 = p0 + 8 * 128;
            *(float2*)p0 = make_float2(SCALEc * acc[i][j][0], SCALEc * acc[i][j][1]);
            *(float2*)p1 = make_float2(SCALEc * acc[i][j][2], SCALEc * acc[i][j][3]);
        }
    }
}

// ---------------- scores term2 + softmax (fused), planes, in-place attn ----------------
__global__ __launch_bounds__(256) void k_scores2_sm(float* __restrict__ scores) {
    __shared__ ushort_t Qh[128][LDK], Ql[128][LDK];
    __shared__ ushort_t Kh[128][LDK], Kl[128][LDK];
    __shared__ float rmax[128][4];
    __shared__ float rsum[128][4];
    const int blk = blockIdx.x;
    const int bh = blk >> 7, fix = blk & 127;       // fix = j
    const int b = bh >> 3, h = bh & 7;
    const int tid = threadIdx.x;
    const int warp = tid >> 5, lane = tid & 31;
    const int wr = warp >> 2, wc = warp & 3;

    const size_t qoff = (size_t)(b * 16384 + fix) * NOUT + h * 64;
    const size_t koff = qoff + 1024;
    const size_t rstride = (size_t)128 * NOUT;

    float acc[4][4][4] = {};
    for (int d0 = 0; d0 < 64; d0 += 16) {
#pragma unroll
        for (int it = 0; it < 2; it++) {
            int idx = it * 256 + tid;
            int r = idx >> 2, q = (idx & 3) * 4;
            size_t o = (size_t)r * rstride + d0 + q;
            ushort4 qh4 = *(const ushort4*)(g_qh + qoff + o);
            ushort4 ql4 = *(const ushort4*)(g_ql + qoff + o);
            ushort4 kh4 = *(const ushort4*)(g_qh + koff + o);
            ushort4 kl4 = *(const ushort4*)(g_ql + koff + o);
            *(ushort2*)&Qh[r][q]     = make_ushort2(qh4.x, qh4.y);
            *(ushort2*)&Qh[r][q + 2] = make_ushort2(qh4.z, qh4.w);
            *(ushort2*)&Ql[r][q]     = make_ushort2(ql4.x, ql4.y);
            *(ushort2*)&Ql[r][q + 2] = make_ushort2(ql4.z, ql4.w);
            *(ushort2*)&Kh[r][q]     = make_ushort2(kh4.x, kh4.y);
            *(ushort2*)&Kh[r][q + 2] = make_ushort2(kh4.z, kh4.w);
            *(ushort2*)&Kl[r][q]     = make_ushort2(kl4.x, kl4.y);
            *(ushort2*)&Kl[r][q + 2] = make_ushort2(kl4.z, kl4.w);
        }
        __syncthreads();
        const int c2 = 2 * (lane & 3), rsel = lane >> 2;
        unsigned ah[4][4], al[4][4], bh2[4][2], bl2[4][2];
#pragma unroll
        for (int i = 0; i < 4; i++) {
            int row = wr * 64 + i * 16 + rsel;
            ah[i][0] = *(const unsigned*)&Qh[row][c2];
            ah[i][1] = *(const unsigned*)&Qh[row + 8][c2];
            ah[i][2] = *(const unsigned*)&Qh[row][c2 + 8];
            ah[i][3] = *(const unsigned*)&Qh[row + 8][c2 + 8];
            al[i][0] = *(const unsigned*)&Ql[row][c2];
            al[i][1] = *(const unsigned*)&Ql[row + 8][c2];
            al[i][2] = *(const unsigned*)&Ql[row][c2 + 8];
            al[i][3] = *(const unsigned*)&Ql[row + 8][c2 + 8];
        }
#pragma unroll
        for (int j = 0; j < 4; j++) {
            int n = wc * 32 + j * 8 + rsel;
            bh2[j][0] = *(const unsigned*)&Kh[n][c2];
            bh2[j][1] = *(const unsigned*)&Kh[n][c2 + 8];
            bl2[j][0] = *(const unsigned*)&Kl[n][c2];
            bl2[j][1] = *(const unsigned*)&Kl[n][c2 + 8];
        }
#pragma unroll
        for (int i = 0; i < 4; i++)
#pragma unroll
            for (int j = 0; j < 4; j++) {
                mma_bf16(acc[i][j], ah[i], bh2[j]);
                mma_bf16(acc[i][j], ah[i], bl2[j]);
                mma_bf16(acc[i][j], al[i], bh2[j]);
            }
        __syncthreads();
    }

    const int rsel = lane >> 2;
    float* base = scores + (size_t)bh * 2097152 + (size_t)fix * 128;
#pragma unroll
    for (int t = 0; t < 4; t++) {
        int row = wr * 64 + t * 16 + rsel;
#pragma unroll
        for (int j = 0; j < 4; j++) {
            int col = wc * 32 + j * 8 + (lane & 3) * 2;
            float2 o0 = *(float2*)(base + (size_t)row * 16384 + col);
            float2 o1 = *(float2*)(base + (size_t)(row + 8) * 16384 + col);
            acc[t][j][0] = SCALEc * acc[t][j][0] + o0.x;
            acc[t][j][1] = SCALEc * acc[t][j][1] + o0.y;
            acc[t][j][2] = SCALEc * acc[t][j][2] + o1.x;
            acc[t][j][3] = SCALEc * acc[t][j][3] + o1.y;
        }
    }
#pragma unroll
    for (int t = 0; t < 4; t++) {
#pragma unroll
        for (int r = 0; r < 2; r++) {
            float m = -1e30f;
#pragma unroll
            for (int j = 0; j < 4; j++)
                m = fmaxf(m, fmaxf(acc[t][j][2 * r], acc[t][j][2 * r + 1]));
            m = fmaxf(m, __shfl_xor_sync(0xffffffffu, m, 1));
            m = fmaxf(m, __shfl_xor_sync(0xffffffffu, m, 2));
            if ((lane & 3) == 0) rmax[wr * 64 + t * 16 + rsel + r * 8][wc] = m;
        }
    }
    __syncthreads();
#pragma unroll
    for (int t = 0; t < 4; t++) {
#pragma unroll
        for (int r = 0; r < 2; r++) {
            int row = wr * 64 + t * 16 + rsel + r * 8;
            float4 mv = *(float4*)rmax[row];
            float gm = fmaxf(fmaxf(mv.x, mv.y), fmaxf(mv.z, mv.w));
            float ls = 0.f;
#pragma unroll
            for (int j = 0; j < 4; j++) {
                float e0 = __expf(acc[t][j][2 * r] - gm);
                float e1 = __expf(acc[t][j][2 * r + 1] - gm);
                acc[t][j][2 * r] = e0; acc[t][j][2 * r + 1] = e1;
                ls += e0 + e1;
            }
            ls += __shfl_xor_sync(0xffffffffu, ls, 1);
            ls += __shfl_xor_sync(0xffffffffu, ls, 2);
            if ((lane & 3) == 0) rsum[row][wc] = ls;
        }
    }
    __syncthreads();
#pragma unroll
    for (int t = 0; t < 4; t++) {
        int row = wr * 64 + t * 16 + rsel;
        float4 s0 = *(float4*)rsum[row];
        float4 s1 = *(float4*)rsum[row + 8];
        float inv0 = 1.f / (s0.x + s0.y + s0.z + s0.w);
        float inv1 = 1.f / (s1.x + s1.y + s1.z + s1.w);
#pragma unroll
        for (int j = 0; j < 4; j++) {
            int col = wc * 32 + j * 8 + (lane & 3) * 2;
            *(float2*)(base + (size_t)row * 16384 + col) =
                make_float2(acc[t][j][0] * inv0, acc[t][j][1] * inv0);
            *(float2*)(base + (size_t)(row + 8) * 16384 + col) =
                make_float2(acc[t][j][2] * inv1, acc[t][j][3] * inv1);
        }
    }
}

// ---------------- output (tf32, attn single + v split; v from fp32) ----------------
#define OPAD 36
#define VPAD 68
template <int MODE>
__global__ __launch_bounds__(256) void k_out_tf(const float* __restrict__ scores,
                                                float* __restrict__ out) {
    __shared__ unsigned As_[128 * OPAD];
    __shared__ unsigned Vh[32 * VPAD];
    __shared__ unsigned Vl[32 * VPAD];
    const int blk = blockIdx.x;
    const int bh = blk >> 7, fix = blk & 127;
    const int b = bh >> 3, h = bh & 7;
    const int tid = threadIdx.x;
    const int warp = tid >> 5, lane = tid & 31;
    const int wr = warp >> 2, wc = warp & 3;

    const float* arow; size_t astride;
    const float* vbase; size_t vstride;
    float* obase; size_t ostride;
    if (MODE == 0) {
        arow = scores + (size_t)blk * 16384;  astride = 128;
        vbase = g_qkv + (size_t)(b * 16384 + fix * 128) * NOUT + 1536 + h * 64;
        vstride = NOUT;
        obase = out + ((size_t)(b * 128 + fix) * 128) * Cc + h * 64;
        ostride = Cc;
    } else {
        arow = scores + (size_t)bh * 2097152 + (size_t)fix * 128;  astride = 16384;
        vbase = g_qkv + (size_t)(b * 16384 + fix) * NOUT + 2048 + h * 64;
        vstride = (size_t)128 * NOUT;
        obase = out + ((size_t)(b * 128) * 128 + fix) * Cc + h * 64;
        ostride = (size_t)128 * Cc;
    }

    float acc[4][2][4] = {};
    for (int k0 = 0; k0 < 128; k0 += 32) {
#pragma unroll
        for (int it = 0; it < 4; it++) {
            int idx = it * 256 + tid;
            int r = idx >> 3, k4 = (idx & 7) * 4;
            float4 av = *(const float4*)(arow + (size_t)r * astride + k0 + k4);
            unsigned* p = &As_[r * OPAD + k4];
            p[0] = f2tf(av.x); p[1] = f2tf(av.y); p[2] = f2tf(av.z); p[3] = f2tf(av.w);
        }
#pragma unroll
        for (int it = 0; it < 2; it++) {
            int idx = it * 256 + tid;
            int k = idx >> 4, d4 = (idx & 15) * 4;
            float4 vv = *(const float4*)(vbase + (size_t)(k0 + k) * vstride + d4);
            unsigned* ph = &Vh[k * VPAD + d4];
            unsigned* pl = &Vl[k * VPAD + d4];
            split_tf(vv.x, ph[0], pl[0]);
            split_tf(vv.y, ph[1], pl[1]);
            split_tf(vv.z, ph[2], pl[2]);
            split_tf(vv.w, ph[3], pl[3]);
        }
        __syncthreads();
#pragma unroll
        for (int ks = 0; ks < 4; ks++) {
            const int kb = ks * 8;
            unsigned a[4][4], bh2[2][2], bl2[2][2];
#pragma unroll
            for (int i = 0; i < 4; i++) {
                int m = wr * 64 + i * 16 + (lane >> 2);
                int c = kb + (lane & 3);
                a[i][0] = As_[m * OPAD + c];
                a[i][1] = As_[(m + 8) * OPAD + c];
                a[i][2] = As_[m * OPAD + c + 4];
                a[i][3] = As_[(m + 8) * OPAD + c + 4];
            }
#pragma unroll
            for (int j = 0; j < 2; j++) {
                int n = wc * 16 + j * 8 + (lane >> 2);
                bh2[j][0] = Vh[(kb + (lane & 3)) * VPAD + n];
                bh2[j][1] = Vh[(kb + (lane & 3) + 4) * VPAD + n];
                bl2[j][0] = Vl[(kb + (lane & 3)) * VPAD + n];
                bl2[j][1] = Vl[(kb + (lane & 3) + 4) * VPAD + n];
            }
#pragma unroll
            for (int i = 0; i < 4; i++)
#pragma unroll
                for (int j = 0; j < 2; j++) {
                    mma_tf32(acc[i][j], a[i], bh2[j]);
                    mma_tf32(acc[i][j], a[i], bl2[j]);
                }
        }
        __syncthreads();
    }
#pragma unroll
    for (int i = 0; i < 4; i++) {
        int row = wr * 64 + i * 16 + (lane >> 2);
#pragma unroll
        for (int j = 0; j < 2; j++) {
            int col = wc * 16 + j * 8 + (lane & 3) * 2;
            float* p0 = obase + (size_t)row * ostride + col;
            float* p1 = obase + (size_t)(row + 8) * ostride + col;
            if (MODE == 0) {
                *(float2*)p0 = make_float2(acc[i][j][0], acc[i][j][1]);
                *(float2*)p1 = make_float2(acc[i][j][2], acc[i][j][3]);
            } else {
                float2 o0 = *(float2*)p0, o1 = *(float2*)p1;
                o0.x += acc[i][j][0]; o0.y += acc[i][j][1];
                o1.x += acc[i][j][2]; o1.y += acc[i][j][3];
                *(float2*)p0 = o0; *(float2*)p1 = o1;
            }
        }
    }
}

// ---------------- launch ----------------
extern "C" void kernel_launch(void* const* d_in, const int* in_sizes, int n_in,
                              void* d_out, int out_size) {
    const float* x = (const float*)d_in[0];
    const float* w = (const float*)d_in[1];
    float* out = (float*)d_out;

    float* scores;
    cudaGetSymbolAddress((void**)&scores, g_scores);

    k_zero<<<1, 1>>>();
    k_reduce<<<1024, 256>>>(x);
    k_finalize<<<1, 1>>>();
    k_prep_x<<<2048, 256>>>(x);
    k_prep_w<<<(NOUT * KDIM + 255) / 256, 256>>>(w);
    k_gemm2<<<dim3(NOUT / 128, MTOT / 128), 256>>>();
    k_scores1<<<4096, 256>>>(scores);
    k_scores2_sm<<<4096, 256>>>(scores);
    k_out_tf<0><<<4096, 256>>>(scores, out);
    k_out_tf<1><<<4096, 256>>>(scores, out);
}